// round 10
// baseline (speedup 1.0000x reference)
#include <cuda_runtime.h>
#include <cstdint>

#define N_ENT   100000
#define D       128
#define NB_SCAN 49
#define AS      65
#define RSTR    128
#define SMEM_BYTES ((256 * 128 + 256 * AS) * 4)

// ---------------- scratch (static, no allocs) ----------------
__device__ float4 g_neigh4[(size_t)N_ENT * 32];
__device__ float  g_WT[256 * 128];                // k-major concat(W_self, W_neigh)
__device__ int    g_cnt[N_ENT];
__device__ int    g_start[N_ENT + 1];
__device__ int    g_head[N_ENT];
__device__ int    g_bsum[64];
__device__ int    g_boff[64];
__device__ float2 g_edge[1600000];

// ---------------- f32x2 helpers ----------------
__device__ __forceinline__ unsigned long long ffma2(unsigned long long a,
                                                    unsigned long long b,
                                                    unsigned long long c) {
    unsigned long long d;
    asm("fma.rn.f32x2 %0, %1, %2, %3;" : "=l"(d) : "l"(a), "l"(b), "l"(c));
    return d;
}
__device__ __forceinline__ unsigned long long pack2(float x, float y) {
    unsigned long long r;
    asm("mov.b64 %0, {%1, %2};" : "=l"(r) : "f"(x), "f"(y));
    return r;
}
__device__ __forceinline__ void unpack2(unsigned long long v, float& x, float& y) {
    asm("mov.b64 {%0, %1}, %2;" : "=f"(x), "=f"(y) : "l"(v));
}

// ---------------- prep: zero cnt + k-major weight transpose ----------------
__global__ void k_prep(const float* __restrict__ Ws, const float* __restrict__ Wn, int n) {
    int i = blockIdx.x * blockDim.x + threadIdx.x;
    if (i < n) g_cnt[i] = 0;
    if (i < 256 * 128) {
        int k = i >> 7, o = i & 127;
        g_WT[i] = (k < 128) ? Ws[o * 128 + k] : Wn[o * 128 + (k - 128)];
    }
}

// ---------------- CSR build ----------------
__global__ void k_hist(const int* __restrict__ rows, int E) {
    int i = blockIdx.x * blockDim.x + threadIdx.x;
    if (i < E) atomicAdd(&g_cnt[rows[i]], 1);
}
__global__ void k_scan1(int n) {
    __shared__ int ss[256];
    int b = blockIdx.x, t = threadIdx.x;
    int base = b * 2048 + t * 8;
    int loc[8], s = 0;
#pragma unroll
    for (int i = 0; i < 8; i++) {
        int idx = base + i;
        loc[i] = (idx < n) ? g_cnt[idx] : 0;
        s += loc[i];
    }
    ss[t] = s;
    __syncthreads();
    for (int off = 1; off < 256; off <<= 1) {
        int v = 0;
        if (t >= off) v = ss[t - off];
        __syncthreads();
        if (t >= off) ss[t] += v;
        __syncthreads();
    }
    int excl = ss[t] - s;
#pragma unroll
    for (int i = 0; i < 8; i++) {
        int idx = base + i;
        if (idx < n) g_start[idx] = excl;
        excl += loc[i];
    }
    if (t == 255) g_bsum[b] = ss[255];
}
__global__ void k_scan2(int nb) {
    __shared__ int ss[64];
    int t = threadIdx.x;
    int v = (t < nb) ? g_bsum[t] : 0;
    ss[t] = v;
    __syncthreads();
    for (int off = 1; off < 64; off <<= 1) {
        int u = 0;
        if (t >= off) u = ss[t - off];
        __syncthreads();
        if (t >= off) ss[t] += u;
        __syncthreads();
    }
    if (t < nb) g_boff[t] = ss[t] - v;
}
__global__ void k_scan3(int n, int E) {
    int i = blockIdx.x * blockDim.x + threadIdx.x;
    if (i < n) {
        int v = g_start[i] + g_boff[i >> 11];
        g_start[i] = v;
        g_head[i] = v;
    }
    if (i == 0) g_start[n] = E;
}
__global__ void k_scatter(const int* __restrict__ rows, const int* __restrict__ cols,
                          const float* __restrict__ vals, int E) {
    int i = blockIdx.x * blockDim.x + threadIdx.x;
    if (i < E) {
        int pos = atomicAdd(&g_head[rows[i]], 1);
        g_edge[pos] = make_float2(__int_as_float(cols[i]), vals[i]);
    }
}

// ---------------- SpMM: warp per row, 8-deep gather pipeline ----------------
__global__ void k_spmm(const float4* __restrict__ embs, int n) {
    int w = (int)((blockIdx.x * blockDim.x + threadIdx.x) >> 5);
    int lane = threadIdx.x & 31;
    if (w >= n) return;
    int s = g_start[w], t = g_start[w + 1];
    float4 acc = make_float4(0.f, 0.f, 0.f, 0.f);
    int e = s;
    for (; e + 8 <= t; e += 8) {
        float2 ed[8];
        float4 rr[8];
#pragma unroll
        for (int q = 0; q < 8; q++) ed[q] = g_edge[e + q];
#pragma unroll
        for (int q = 0; q < 8; q++)
            rr[q] = embs[(size_t)__float_as_int(ed[q].x) * 32 + lane];
#pragma unroll
        for (int q = 0; q < 8; q++) {
            acc.x += ed[q].y * rr[q].x;
            acc.y += ed[q].y * rr[q].y;
            acc.z += ed[q].y * rr[q].z;
            acc.w += ed[q].y * rr[q].w;
        }
    }
    for (; e < t; e++) {
        float2 ed = g_edge[e];
        float4 r = embs[(size_t)__float_as_int(ed.x) * 32 + lane];
        acc.x += ed.y * r.x; acc.y += ed.y * r.y;
        acc.z += ed.y * r.z; acc.w += ed.y * r.w;
    }
    g_neigh4[(size_t)w * 32 + lane] = acc;
}

// ---------------- GEMM: r2 core, persistent (W loaded once per CTA) ----------------
// out = leaky( [x | neigh] @ WT + bs + bn ), K = 256, tile 64 rows x 128 cols.
__global__ __launch_bounds__(256, 1)
void k_gemm(const float* __restrict__ x,
            const float* __restrict__ bs,
            const float* __restrict__ bn,
            float* __restrict__ out, int N) {
    extern __shared__ float sm[];
    float* sW = sm;                 // [256 k][128 c]
    float* sA = sm + 256 * 128;     // [256 k][AS] ; also hosts red[64][RSTR]
    const float* neigh = (const float*)g_neigh4;
    int tid = threadIdx.x;
    int tc = tid & 15;              // col group: cols tc*8 .. tc*8+7
    int tr = (tid >> 4) & 7;        // row group: rows tr*8 .. tr*8+7
    int kh = tid >> 7;              // split-K half: k in [kh*128, kh*128+128)

    // weights: one 128KB coalesced copy, lives for the whole kernel
    {
        const float4* wt4 = (const float4*)g_WT;
        float4* sW4 = (float4*)sW;
#pragma unroll
        for (int i = 0; i < 32; i++) sW4[tid + i * 256] = wt4[tid + i * 256];
    }
    // bias for this thread's cols (uniform loads, once)
    float bb[8];
#pragma unroll
    for (int j = 0; j < 8; j++) {
        int c = tc * 8 + j;
        bb[j] = bs[c] + bn[c];
    }

    int ntiles = (N + 63) >> 6;
    int k0 = kh * 128;
    for (int tile = blockIdx.x; tile < ntiles; tile += gridDim.x) {
        int base = tile << 6;
        __syncthreads();            // prev epilogue (reads red in sA) done
        // A tile: row it, k = tid (coalesced reads; stride-65 STS conflict-free)
        for (int it = 0; it < 64; it++) {
            int gr = base + it;
            float v = 0.f;
            if (gr < N) {
                v = (tid < 128) ? x[(size_t)gr * 128 + tid]
                                : neigh[(size_t)gr * 128 + (tid - 128)];
            }
            sA[tid * AS + it] = v;
        }
        __syncthreads();

        unsigned long long acc[8][4];
#pragma unroll
        for (int i = 0; i < 8; i++)
#pragma unroll
            for (int j = 0; j < 4; j++) acc[i][j] = 0ull;

#pragma unroll 4
        for (int kk = 0; kk < 128; kk++) {
            int k = k0 + kk;
            const float* wr = sW + k * 128 + tc * 8;
            float4 w0 = *(const float4*)wr;
            float4 w1 = *(const float4*)(wr + 4);
            unsigned long long w2[4];
            w2[0] = pack2(w0.x, w0.y); w2[1] = pack2(w0.z, w0.w);
            w2[2] = pack2(w1.x, w1.y); w2[3] = pack2(w1.z, w1.w);
            const float* ar = sA + k * AS + tr * 8;
#pragma unroll
            for (int i = 0; i < 8; i++) {
                float av = ar[i];
                unsigned long long a2 = pack2(av, av);
#pragma unroll
                for (int j = 0; j < 4; j++) acc[i][j] = ffma2(a2, w2[j], acc[i][j]);
            }
        }

        // cross-half reduction through sA region (sA consumed; sW preserved)
        __syncthreads();
        float* red = sA;            // [64][RSTR]
        if (kh == 1) {
#pragma unroll
            for (int i = 0; i < 8; i++) {
                float v[8];
#pragma unroll
                for (int j = 0; j < 4; j++) unpack2(acc[i][j], v[2 * j], v[2 * j + 1]);
                float* rp = red + (tr * 8 + i) * RSTR + tc * 8;
                *(float4*)rp = make_float4(v[0], v[1], v[2], v[3]);
                *(float4*)(rp + 4) = make_float4(v[4], v[5], v[6], v[7]);
            }
        }
        __syncthreads();
        if (kh == 0) {
#pragma unroll
            for (int i = 0; i < 8; i++) {
                int gr = base + tr * 8 + i;
                if (gr >= N) continue;
                float v[8];
#pragma unroll
                for (int j = 0; j < 4; j++) unpack2(acc[i][j], v[2 * j], v[2 * j + 1]);
                const float* rp = red + (tr * 8 + i) * RSTR + tc * 8;
#pragma unroll
                for (int j = 0; j < 8; j++) {
                    float t = v[j] + rp[j] + bb[j];
                    v[j] = t > 0.f ? t : 0.01f * t;
                }
                float* op = out + (size_t)gr * 128 + tc * 8;
                *(float4*)op = make_float4(v[0], v[1], v[2], v[3]);
                *(float4*)(op + 4) = make_float4(v[4], v[5], v[6], v[7]);
            }
        }
    }
}

extern "C" void kernel_launch(void* const* d_in, const int* in_sizes, int n_in,
                              void* d_out, int out_size) {
    const float* embs = (const float*)d_in[0];
    const int*   rows = (const int*)d_in[1];
    const int*   cols = (const int*)d_in[2];
    const float* vals = (const float*)d_in[3];
    const float* Ws   = (const float*)d_in[4];
    const float* bs   = (const float*)d_in[5];
    const float* Wn   = (const float*)d_in[6];
    const float* bn   = (const float*)d_in[7];
    float* out = (float*)d_out;

    int N = in_sizes[0] / D;
    int E = in_sizes[1];

    cudaFuncSetAttribute(k_gemm, cudaFuncAttributeMaxDynamicSharedMemorySize, SMEM_BYTES);

    k_prep<<<(N + 255) / 256, 256>>>(Ws, Wn, N);
    k_hist<<<(E + 255) / 256, 256>>>(rows, E);
    k_scan1<<<NB_SCAN, 256>>>(N);
    k_scan2<<<1, 64>>>(NB_SCAN);
    k_scan3<<<(N + 255) / 256, 256>>>(N, E);
    k_scatter<<<(E + 255) / 256, 256>>>(rows, cols, vals, E);
    k_spmm<<<(N + 7) / 8, 256>>>((const float4*)embs, N);
    k_gemm<<<148, 256, SMEM_BYTES>>>(embs, bs, bn, out, N);
}

// round 11
// speedup vs baseline: 2.0615x; 2.0615x over previous
#include <cuda_runtime.h>
#include <cstdint>

#define N_ENT   100000
#define D       128
#define NB_SCAN 49
#define AS      65
#define GSMEM   ((128 * 128 + 128 * AS) * 4)

// ---------------- scratch (static, no allocs) ----------------
__device__ float4 g_neigh4[(size_t)N_ENT * 32];
__device__ float  g_WT[256 * 128];                // k-major concat(W_self, W_neigh)
__device__ int    g_cnt[N_ENT];
__device__ int    g_start[N_ENT + 1];
__device__ int    g_head[N_ENT];
__device__ int    g_bsum[64];
__device__ int    g_boff[64];
__device__ float2 g_edge[1600000];

// ---------------- f32x2 helpers ----------------
__device__ __forceinline__ unsigned long long ffma2(unsigned long long a,
                                                    unsigned long long b,
                                                    unsigned long long c) {
    unsigned long long d;
    asm("fma.rn.f32x2 %0, %1, %2, %3;" : "=l"(d) : "l"(a), "l"(b), "l"(c));
    return d;
}
__device__ __forceinline__ unsigned long long pack2(float x, float y) {
    unsigned long long r;
    asm("mov.b64 %0, {%1, %2};" : "=l"(r) : "f"(x), "f"(y));
    return r;
}
__device__ __forceinline__ void unpack2(unsigned long long v, float& x, float& y) {
    asm("mov.b64 {%0, %1}, %2;" : "=f"(x), "=f"(y) : "l"(v));
}

// ---------------- weight transpose (k-major) ----------------
__global__ void k_transpose(const float* __restrict__ Ws, const float* __restrict__ Wn) {
    int idx = blockIdx.x * blockDim.x + threadIdx.x;
    if (idx >= 256 * 128) return;
    int k = idx >> 7, o = idx & 127;
    g_WT[idx] = (k < 128) ? Ws[o * 128 + k] : Wn[o * 128 + (k - 128)];
}

// ---------------- CSR build ----------------
__global__ void k_zero_cnt(int n) {
    int i = blockIdx.x * blockDim.x + threadIdx.x;
    if (i < n) g_cnt[i] = 0;
}
__global__ void k_hist(const int* __restrict__ rows, int E) {
    int i = blockIdx.x * blockDim.x + threadIdx.x;
    if (i < E) atomicAdd(&g_cnt[rows[i]], 1);
}
__global__ void k_scan1(int n) {
    __shared__ int ss[256];
    int b = blockIdx.x, t = threadIdx.x;
    int base = b * 2048 + t * 8;
    int loc[8], s = 0;
#pragma unroll
    for (int i = 0; i < 8; i++) {
        int idx = base + i;
        loc[i] = (idx < n) ? g_cnt[idx] : 0;
        s += loc[i];
    }
    ss[t] = s;
    __syncthreads();
    for (int off = 1; off < 256; off <<= 1) {
        int v = 0;
        if (t >= off) v = ss[t - off];
        __syncthreads();
        if (t >= off) ss[t] += v;
        __syncthreads();
    }
    int excl = ss[t] - s;
#pragma unroll
    for (int i = 0; i < 8; i++) {
        int idx = base + i;
        if (idx < n) g_start[idx] = excl;
        excl += loc[i];
    }
    if (t == 255) g_bsum[b] = ss[255];
}
__global__ void k_scan2(int nb) {
    __shared__ int ss[64];
    int t = threadIdx.x;
    int v = (t < nb) ? g_bsum[t] : 0;
    ss[t] = v;
    __syncthreads();
    for (int off = 1; off < 64; off <<= 1) {
        int u = 0;
        if (t >= off) u = ss[t - off];
        __syncthreads();
        if (t >= off) ss[t] += u;
        __syncthreads();
    }
    if (t < nb) g_boff[t] = ss[t] - v;
}
__global__ void k_scan3(int n, int E) {
    int i = blockIdx.x * blockDim.x + threadIdx.x;
    if (i < n) {
        int v = g_start[i] + g_boff[i >> 11];
        g_start[i] = v;
        g_head[i] = v;
    }
    if (i == 0) g_start[n] = E;
}
__global__ void k_scatter(const int* __restrict__ rows, const int* __restrict__ cols,
                          const float* __restrict__ vals, int E) {
    int i = blockIdx.x * blockDim.x + threadIdx.x;
    if (i < E) {
        int pos = atomicAdd(&g_head[rows[i]], 1);
        g_edge[pos] = make_float2(__int_as_float(cols[i]), vals[i]);
    }
}
__global__ void k_spmm(const float4* __restrict__ embs, int n) {
    int w = (int)((blockIdx.x * blockDim.x + threadIdx.x) >> 5);
    int lane = threadIdx.x & 31;
    if (w >= n) return;
    int s = g_start[w], t = g_start[w + 1];
    float4 acc = make_float4(0.f, 0.f, 0.f, 0.f);
    int e = s;
    for (; e + 4 <= t; e += 4) {
        float2 e0 = g_edge[e], e1 = g_edge[e + 1], e2 = g_edge[e + 2], e3 = g_edge[e + 3];
        float4 r0 = embs[(size_t)__float_as_int(e0.x) * 32 + lane];
        float4 r1 = embs[(size_t)__float_as_int(e1.x) * 32 + lane];
        float4 r2 = embs[(size_t)__float_as_int(e2.x) * 32 + lane];
        float4 r3 = embs[(size_t)__float_as_int(e3.x) * 32 + lane];
        acc.x += e0.y * r0.x + e1.y * r1.x + e2.y * r2.x + e3.y * r3.x;
        acc.y += e0.y * r0.y + e1.y * r1.y + e2.y * r2.y + e3.y * r3.y;
        acc.z += e0.y * r0.z + e1.y * r1.z + e2.y * r2.z + e3.y * r3.z;
        acc.w += e0.y * r0.w + e1.y * r1.w + e2.y * r2.w + e3.y * r3.w;
    }
    for (; e < t; e++) {
        float2 ed = g_edge[e];
        float4 r = embs[(size_t)__float_as_int(ed.x) * 32 + lane];
        acc.x += ed.y * r.x; acc.y += ed.y * r.y;
        acc.z += ed.y * r.z; acc.w += ed.y * r.w;
    }
    g_neigh4[(size_t)w * 32 + lane] = acc;
}

// ---------------- GEMM half (r2 core, K=128 per kernel) ----------------
// HALF=0: out = x @ Ws^T + (bs + bn)            (runs overlapped with chain)
// HALF=1: out = leaky(out + neigh @ Wn^T)       (after spmm + half 0)
template <int HALF>
__global__ __launch_bounds__(256)
void k_gemm(const float* __restrict__ A0,
            const float* __restrict__ bs,
            const float* __restrict__ bn,
            float* __restrict__ out, int N) {
    extern __shared__ float sm[];
    float* sW = sm;                 // [128 k][128 c]
    float* sA = sm + 128 * 128;     // [128 k][AS]; reused as red[64][128]
    const float* src = HALF ? (const float*)g_neigh4 : A0;
    int tid = threadIdx.x;
    int tc = tid & 15;              // col group: cols tc*8 .. tc*8+7
    int tr = (tid >> 4) & 7;        // row group: rows tr*8 .. tr*8+7
    int kh = tid >> 7;              // split-K half: k in [kh*64, kh*64+64)
    int base = blockIdx.x * 64;

    // weights: 64KB coalesced copy of this half's slab
    {
        const float4* wt4 = (const float4*)(g_WT + HALF * 128 * 128);
        float4* sW4 = (float4*)sW;
#pragma unroll
        for (int i = 0; i < 16; i++) sW4[tid + i * 256] = wt4[tid + i * 256];
    }
    // A tile: 64 rows x 128 k; threads split (k = tid&127, row parity = tid>>7)
    for (int it = 0; it < 32; it++) {
        int r = it * 2 + (tid >> 7);
        int k = tid & 127;
        int gr = base + r;
        float v = (gr < N) ? src[(size_t)gr * 128 + k] : 0.f;
        sA[k * AS + r] = v;
    }
    __syncthreads();

    unsigned long long acc[8][4];
#pragma unroll
    for (int i = 0; i < 8; i++)
#pragma unroll
        for (int j = 0; j < 4; j++) acc[i][j] = 0ull;

    int k0 = kh * 64;
#pragma unroll 4
    for (int kk = 0; kk < 64; kk++) {
        int k = k0 + kk;
        const float* wr = sW + k * 128 + tc * 8;
        float4 w0 = *(const float4*)wr;
        float4 w1 = *(const float4*)(wr + 4);
        unsigned long long w2[4];
        w2[0] = pack2(w0.x, w0.y); w2[1] = pack2(w0.z, w0.w);
        w2[2] = pack2(w1.x, w1.y); w2[3] = pack2(w1.z, w1.w);
        const float* ar = sA + k * AS + tr * 8;
#pragma unroll
        for (int i = 0; i < 8; i++) {
            float av = ar[i];
            unsigned long long a2 = pack2(av, av);
#pragma unroll
            for (int j = 0; j < 4; j++) acc[i][j] = ffma2(a2, w2[j], acc[i][j]);
        }
    }

    // cross-half reduction through sA region (sW preserved but unused after)
    __syncthreads();
    float* red = sA;                // [64][128]
    if (kh == 1) {
#pragma unroll
        for (int i = 0; i < 8; i++) {
            float v[8];
#pragma unroll
            for (int j = 0; j < 4; j++) unpack2(acc[i][j], v[2 * j], v[2 * j + 1]);
            float* rp = red + (tr * 8 + i) * 128 + tc * 8;
            *(float4*)rp = make_float4(v[0], v[1], v[2], v[3]);
            *(float4*)(rp + 4) = make_float4(v[4], v[5], v[6], v[7]);
        }
    }
    __syncthreads();
    if (kh == 0) {
        float bb[8];
        if (!HALF) {
#pragma unroll
            for (int j = 0; j < 8; j++) {
                int c = tc * 8 + j;
                bb[j] = bs[c] + bn[c];
            }
        }
#pragma unroll
        for (int i = 0; i < 8; i++) {
            int gr = base + tr * 8 + i;
            if (gr >= N) continue;
            float v[8];
#pragma unroll
            for (int j = 0; j < 4; j++) unpack2(acc[i][j], v[2 * j], v[2 * j + 1]);
            const float* rp = red + (tr * 8 + i) * 128 + tc * 8;
            float* op = out + (size_t)gr * 128 + tc * 8;
            if (HALF) {
                float4 o0 = *(const float4*)op;
                float4 o1 = *(const float4*)(op + 4);
                float oo[8] = {o0.x, o0.y, o0.z, o0.w, o1.x, o1.y, o1.z, o1.w};
#pragma unroll
                for (int j = 0; j < 8; j++) {
                    float t = v[j] + rp[j] + oo[j];
                    v[j] = t > 0.f ? t : 0.01f * t;
                }
            } else {
#pragma unroll
                for (int j = 0; j < 8; j++) v[j] += rp[j] + bb[j];
            }
            *(float4*)op = make_float4(v[0], v[1], v[2], v[3]);
            *(float4*)(op + 4) = make_float4(v[4], v[5], v[6], v[7]);
        }
    }
}

extern "C" void kernel_launch(void* const* d_in, const int* in_sizes, int n_in,
                              void* d_out, int out_size) {
    const float* embs = (const float*)d_in[0];
    const int*   rows = (const int*)d_in[1];
    const int*   cols = (const int*)d_in[2];
    const float* vals = (const float*)d_in[3];
    const float* Ws   = (const float*)d_in[4];
    const float* bs   = (const float*)d_in[5];
    const float* Wn   = (const float*)d_in[6];
    const float* bn   = (const float*)d_in[7];
    float* out = (float*)d_out;

    int N = in_sizes[0] / D;
    int E = in_sizes[1];

    static cudaStream_t s2 = nullptr;
    static cudaEvent_t evA = nullptr, evB = nullptr;
    if (!s2) {
        cudaStreamCreateWithFlags(&s2, cudaStreamNonBlocking);
        cudaEventCreateWithFlags(&evA, cudaEventDisableTiming);
        cudaEventCreateWithFlags(&evB, cudaEventDisableTiming);
    }

    cudaFuncSetAttribute(k_gemm<0>, cudaFuncAttributeMaxDynamicSharedMemorySize, GSMEM);
    cudaFuncSetAttribute(k_gemm<1>, cudaFuncAttributeMaxDynamicSharedMemorySize, GSMEM);

    int gtiles = (N + 63) / 64;

    // weights first (both branches need g_WT)
    k_transpose<<<(256 * 128 + 255) / 256, 256>>>(Ws, Wn);

    // fork: self-half GEMM on side stream
    cudaEventRecord(evA, 0);
    cudaStreamWaitEvent(s2, evA, 0);
    k_gemm<0><<<gtiles, 256, GSMEM, s2>>>(embs, bs, bn, out, N);

    // CSR/SpMM chain on default stream
    k_zero_cnt<<<(N + 255) / 256, 256>>>(N);
    k_hist<<<(E + 255) / 256, 256>>>(rows, E);
    k_scan1<<<NB_SCAN, 256>>>(N);
    k_scan2<<<1, 64>>>(NB_SCAN);
    k_scan3<<<(N + 255) / 256, 256>>>(N, E);
    k_scatter<<<(E + 255) / 256, 256>>>(rows, cols, vals, E);
    k_spmm<<<(N + 7) / 8, 256>>>((const float4*)embs, N);

    // join, then neighbor-half GEMM fuses add + leaky
    cudaEventRecord(evB, s2);
    cudaStreamWaitEvent(0, evB, 0);
    k_gemm<1><<<gtiles, 256, GSMEM>>>(nullptr, nullptr, nullptr, out, N);
}